// round 17
// baseline (speedup 1.0000x reference)
#include <cuda_runtime.h>
#include <cuda_fp16.h>
#include <cstdint>

#define BB   4
#define NPQ  1024
#define NRK  1024
#define CDIM 1024
#define HH   16
#define DH   64

// Scratch (static device arrays: allocation-guard safe)
__device__ __half g_Qh[(size_t)BB * NPQ * CDIM];
__device__ __half g_Kh[(size_t)BB * NRK * CDIM];
__device__ __half g_Wh[3 * (size_t)CDIM * CDIM];
__device__ __half g_q[(size_t)BB * NPQ * CDIM];
__device__ __half g_k[(size_t)BB * NRK * CDIM];
__device__ __half g_v[(size_t)BB * NRK * CDIM];
__device__ __half g_P[(size_t)BB * HH * NPQ * NRK];   // 128 MB
__device__ float  g_rowsum[(size_t)BB * HH * NPQ];

// ---------------------------------------------------------------------------
__device__ __forceinline__ uint32_t h2_bits(__half2 h) {
    return *reinterpret_cast<uint32_t*>(&h);
}

__device__ __forceinline__ void mma_f16(float c[4], const uint32_t a[4],
                                        const uint32_t b[2]) {
    asm volatile(
        "mma.sync.aligned.m16n8k16.row.col.f32.f16.f16.f32 "
        "{%0,%1,%2,%3}, {%4,%5,%6,%7}, {%8,%9}, {%0,%1,%2,%3};"
        : "+f"(c[0]), "+f"(c[1]), "+f"(c[2]), "+f"(c[3])
        : "r"(a[0]), "r"(a[1]), "r"(a[2]), "r"(a[3]), "r"(b[0]), "r"(b[1]));
}

#define LDSM_X4(r, addr) \
    asm volatile("ldmatrix.sync.aligned.m8n8.x4.shared.b16 {%0,%1,%2,%3}, [%4];" \
        : "=r"((r)[0]), "=r"((r)[1]), "=r"((r)[2]), "=r"((r)[3]) : "r"(addr))
#define LDSM_X2(r, addr) \
    asm volatile("ldmatrix.sync.aligned.m8n8.x2.shared.b16 {%0,%1}, [%2];" \
        : "=r"((r)[0]), "=r"((r)[1]) : "r"(addr))
#define LDSM_X2_T(r, addr) \
    asm volatile("ldmatrix.sync.aligned.m8n8.x2.trans.shared.b16 {%0,%1}, [%2];" \
        : "=r"((r)[0]), "=r"((r)[1]) : "r"(addr))

__device__ __forceinline__ uint32_t smem_u32(const void* p) {
    uint32_t a;
    asm("{ .reg .u64 t; cvta.to.shared.u64 t, %1; cvt.u32.u64 %0, t; }"
        : "=r"(a) : "l"(p));
    return a;
}

#define CP_ASYNC16(dst, src) \
    asm volatile("cp.async.cg.shared.global [%0], [%1], 16;" \
                 :: "r"(dst), "l"(src) : "memory")
#define CP_COMMIT() asm volatile("cp.async.commit_group;" ::: "memory")
#define CP_WAIT1()  asm volatile("cp.async.wait_group 1;" ::: "memory")
#define CP_WAIT0()  asm volatile("cp.async.wait_group 0;" ::: "memory")

#define SCH 72    // q/k smem halves stride
#define VSH 72    // v smem halves stride
#define PH  40    // proj A/B halves stride

// fused kernel smem layout (halves): q-tile 64 rows, kv chunks 128 rows x2buf
#define FQ_OFF 0
#define FK_OFF (64 * SCH)
#define FV_OFF (FK_OFF + 2 * 128 * SCH)
#define FR_OFF (FV_OFF + 2 * 128 * VSH)
#define F_SMEM ((FR_OFF + 128) * 2)         // 83200 B -> 2 CTAs/SM

// ---------------------------------------------------------------------------
// Merged fp32 -> fp16 conversion (one launch over 5 regions)
// ---------------------------------------------------------------------------
__global__ void __launch_bounds__(256) f2h_all(
    const float* __restrict__ Q, const float* __restrict__ K,
    const float* __restrict__ Wq, const float* __restrict__ Wk,
    const float* __restrict__ Wv,
    __half* __restrict__ Qh, __half* __restrict__ Kh, __half* __restrict__ Wh)
{
    const int NX4 = (BB * NPQ * CDIM) / 4;
    const int NW4 = (CDIM * CDIM) / 4;
    int i = blockIdx.x * 256 + threadIdx.x;

    const float* src;
    __half* dst;
    int off;
    if (i < NX4)                  { src = Q;  dst = Qh; off = i; }
    else if (i < 2 * NX4)         { src = K;  dst = Kh; off = i - NX4; }
    else if (i < 2 * NX4 + NW4)   { src = Wq; dst = Wh; off = i - 2 * NX4; }
    else if (i < 2 * NX4 + 2*NW4) { src = Wk; dst = Wh + (size_t)CDIM * CDIM;
                                    off = i - 2 * NX4 - NW4; }
    else if (i < 2 * NX4 + 3*NW4) { src = Wv; dst = Wh + 2 * (size_t)CDIM * CDIM;
                                    off = i - 2 * NX4 - 2 * NW4; }
    else return;

    float4 v = reinterpret_cast<const float4*>(src)[off];
    __half2* o = reinterpret_cast<__half2*>(dst) + 2 * (size_t)off;
    o[0] = __floats2half2_rn(v.x, v.y);
    o[1] = __floats2half2_rn(v.z, v.w);
}

// ---------------------------------------------------------------------------
// Projection GEMM (NT, fp16 HMMA), batched z in {0,1,2}. [R13]
// ---------------------------------------------------------------------------
__global__ void __launch_bounds__(256, 2) proj_gemm(
    const __half* __restrict__ Qh, const __half* __restrict__ Kh,
    const __half* __restrict__ Wh,
    const float* __restrict__ bq, const float* __restrict__ bk,
    const float* __restrict__ bv,
    __half* __restrict__ qo, __half* __restrict__ ko, __half* __restrict__ vo)
{
    extern __shared__ __half sh[];
    __half* Ah = sh;
    __half* Bh = sh + 128 * PH;

    const int zz = blockIdx.z;
    const __half* Ag = (zz == 0) ? Qh : Kh;
    const __half* Bg = Wh + (size_t)zz * CDIM * CDIM;
    const float* bias = (zz == 0) ? bq : ((zz == 1) ? bk : bv);
    __half* Cg = (zz == 0) ? qo : ((zz == 1) ? ko : vo);

    const int tid = threadIdx.x;
    const int m0 = blockIdx.y << 7, n0 = blockIdx.x << 7;
    const int warp = tid >> 5, lane = tid & 31;
    const int g = lane >> 2, t = lane & 3;
    const int wm = (warp >> 1) << 5;
    const int wn = (warp & 1) << 6;

    const uint32_t sA = smem_u32(Ah);
    const uint32_t sB = smem_u32(Bh);

    auto load_stage = [&](int kt) {
        const int so = (kt & 1) << 4;
        const int k0 = kt << 4;
        int r = tid >> 1, c = (tid & 1) << 3;
        CP_ASYNC16(sA + ((r * PH + so + c) << 1),
                   Ag + (size_t)(m0 + r) * CDIM + k0 + c);
        CP_ASYNC16(sB + ((r * PH + so + c) << 1),
                   Bg + (size_t)(n0 + r) * CDIM + k0 + c);
        CP_COMMIT();
    };

    float acc[2][8][4];
#pragma unroll
    for (int i = 0; i < 2; i++)
#pragma unroll
        for (int j = 0; j < 8; j++)
#pragma unroll
            for (int l = 0; l < 4; l++) acc[i][j][l] = 0.f;

    const int KT = CDIM / 16;
    load_stage(0);

    const int arow = lane & 15, acol = (lane >> 4) << 3;
    const int brow = lane & 7,  bcol = ((lane >> 3) & 1) << 3;

    for (int kt = 0; kt < KT; kt++) {
        const bool pf = (kt + 1 < KT);
        if (pf) { load_stage(kt + 1); CP_WAIT1(); } else { CP_WAIT0(); }
        __syncthreads();

        const int so = (kt & 1) << 4;
        uint32_t a[2][4], b[8][2];
#pragma unroll
        for (int mt = 0; mt < 2; mt++)
            LDSM_X4(a[mt], sA + (((wm + (mt << 4) + arow) * PH) + so + acol) * 2);
#pragma unroll
        for (int nt = 0; nt < 8; nt++)
            LDSM_X2(b[nt], sB + (((wn + (nt << 3) + brow) * PH) + so + bcol) * 2);
#pragma unroll
        for (int mt = 0; mt < 2; mt++)
#pragma unroll
            for (int nt = 0; nt < 8; nt++)
                mma_f16(acc[mt][nt], a[mt], b[nt]);
        __syncthreads();
    }

#pragma unroll
    for (int mt = 0; mt < 2; mt++) {
        int m = m0 + wm + (mt << 4) + g;
#pragma unroll
        for (int nt = 0; nt < 8; nt++) {
            int n = n0 + wn + (nt << 3) + 2 * t;
            float b0v = bias[n], b1v = bias[n + 1];
            *reinterpret_cast<__half2*>(Cg + (size_t)m * CDIM + n) =
                __floats2half2_rn(acc[mt][nt][0] + b0v, acc[mt][nt][1] + b1v);
            *reinterpret_cast<__half2*>(Cg + (size_t)(m + 8) * CDIM + n) =
                __floats2half2_rn(acc[mt][nt][2] + b0v, acc[mt][nt][3] + b1v);
        }
    }
}

// ---------------------------------------------------------------------------
// Fused scores + PV, FA2 register-fragment P.
// 128 threads, 4 warps (2m x 2ks), q-tile 64 rows, kv chunks 128 rows.
// 2 CTAs/SM co-resident: one CTA's exp/MUFU phase overlaps the other's HMMA.
// ---------------------------------------------------------------------------
__global__ void __launch_bounds__(128, 2) fused_spv(
    const __half* __restrict__ qg, const __half* __restrict__ kg,
    const __half* __restrict__ vg,
    __half* __restrict__ Pg, float* __restrict__ rowsum,
    float* __restrict__ Og)
{
    extern __shared__ __half sh[];
    __half* qs = sh + FQ_OFF;
    float* rows_s = reinterpret_cast<float*>(sh + FR_OFF);   // 64 floats

    const int tid = threadIdx.x;
    const int z = blockIdx.y;
    const long long zb = z >> 4, zh = z & 15;
    const __half* Aq = qg + zb * ((long long)NPQ * CDIM) + zh * DH;
    const __half* Ak = kg + zb * ((long long)NRK * CDIM) + zh * DH;
    const __half* Av = vg + zb * ((long long)NRK * CDIM) + zh * DH;
    __half* Pz = Pg + (long long)z * NPQ * NRK;
    float* Oz = Og + zb * ((long long)NPQ * CDIM) + zh * DH;

    const int m0 = blockIdx.x << 6;       // q-tile 64
    const int warp = tid >> 5, lane = tid & 31;
    const int g = lane >> 2, t = lane & 3;
    const int wm  = (warp >> 1) << 5;     // 0,32
    const int wnS = (warp & 1) << 6;      // 0,64 : S cols = PV k-slice

    const uint32_t sq = smem_u32(qs);
    const uint32_t sk = smem_u32(sh + FK_OFF);
    const uint32_t sv = smem_u32(sh + FV_OFF);

    // kv loader: thread = row (0..127), 8x16B per operand
    auto load_kv = [&](int rc) {
        const int s = rc & 1;
        const int rbase = rc << 7;
        const __half* pk = Ak + (size_t)(rbase + tid) * CDIM;
        const __half* pv = Av + (size_t)(rbase + tid) * CDIM;
        const uint32_t dk = sk + ((s * 128 * SCH + tid * SCH) << 1);
        const uint32_t dv = sv + ((s * 128 * VSH + tid * VSH) << 1);
#pragma unroll
        for (int i = 0; i < 8; i++) {
            CP_ASYNC16(dk + (i << 4), pk + (i << 3));
            CP_ASYNC16(dv + (i << 4), pv + (i << 3));
        }
        CP_COMMIT();
    };

    // q tile (64 rows): thread covers row tid>>1, half lh
    {
        const int lrow = tid >> 1;
        const int lh = (tid & 1) << 5;
        const __half* pa = Aq + (size_t)(m0 + lrow) * CDIM + lh;
        const uint32_t dq = sq + ((lrow * SCH + lh) << 1);
#pragma unroll
        for (int i = 0; i < 4; i++)
            CP_ASYNC16(dq + (i << 4), pa + (i << 3));
    }
    load_kv(0);

    if (tid < 64) rows_s[tid] = 0.f;

    float oacc[2][8][4];
#pragma unroll
    for (int i = 0; i < 2; i++)
#pragma unroll
        for (int j = 0; j < 8; j++)
#pragma unroll
            for (int l = 0; l < 4; l++) oacc[i][j][l] = 0.f;

    float rsum[2][2] = {{0.f, 0.f}, {0.f, 0.f}};

    const int arow = lane & 15, acol = (lane >> 4) << 3;
    const int brow = lane & 7,  bcol = ((lane >> 3) & 1) << 3;
    const int bkrow = lane & 15;
    const float alpha = 0.03125f;

    for (int rc = 0; rc < 8; rc++) {
        const int s = rc & 1;
        if (rc + 1 < 8) { load_kv(rc + 1); CP_WAIT1(); } else { CP_WAIT0(); }
        __syncthreads();

        // ---- S = q.k^T (warp: 32x64, K=64) ----
        float sacc[2][8][4];
#pragma unroll
        for (int i = 0; i < 2; i++)
#pragma unroll
            for (int j = 0; j < 8; j++)
#pragma unroll
                for (int l = 0; l < 4; l++) sacc[i][j][l] = 0.f;

#pragma unroll
        for (int kk = 0; kk < 64; kk += 16) {
            uint32_t a[2][4], b[8][2];
#pragma unroll
            for (int mt = 0; mt < 2; mt++)
                LDSM_X4(a[mt],
                        sq + (((wm + (mt << 4) + arow) * SCH) + kk + acol) * 2);
#pragma unroll
            for (int nt = 0; nt < 8; nt++)
                LDSM_X2(b[nt],
                        sk + ((s * 128 * SCH +
                               (wnS + (nt << 3) + brow) * SCH) + kk + bcol) * 2);
#pragma unroll
            for (int mt = 0; mt < 2; mt++)
#pragma unroll
                for (int nt = 0; nt < 8; nt++)
                    mma_f16(sacc[mt][nt], a[mt], b[nt]);
        }

        // ---- exp -> P gmem + register A-fragments (FA2) ----
        const int rbase = rc << 7;
        uint32_t pa[2][4][4];
#pragma unroll
        for (int mt = 0; mt < 2; mt++) {
            int mloc = wm + (mt << 4) + g;
#pragma unroll
            for (int j = 0; j < 4; j++) {
#pragma unroll
                for (int e = 0; e < 2; e++) {
                    int nt = 2 * j + e;
                    float e0 = __expf(sacc[mt][nt][0] * alpha);
                    float e1 = __expf(sacc[mt][nt][1] * alpha);
                    float e2 = __expf(sacc[mt][nt][2] * alpha);
                    float e3 = __expf(sacc[mt][nt][3] * alpha);
                    rsum[mt][0] += e0 + e1;
                    rsum[mt][1] += e2 + e3;
                    __half2 p01 = __floats2half2_rn(e0, e1);
                    __half2 p23 = __floats2half2_rn(e2, e3);
                    int n = wnS + (nt << 3) + 2 * t;
                    *reinterpret_cast<__half2*>(
                        Pz + (size_t)(m0 + mloc) * NRK + rbase + n) = p01;
                    *reinterpret_cast<__half2*>(
                        Pz + (size_t)(m0 + mloc + 8) * NRK + rbase + n) = p23;
                    pa[mt][j][2 * e]     = h2_bits(p01);
                    pa[mt][j][2 * e + 1] = h2_bits(p23);
                }
            }
        }

        // ---- O += P @ V over this warp's k-slice (wnS..wnS+63) ----
#pragma unroll
        for (int j = 0; j < 4; j++) {
            uint32_t b[8][2];
#pragma unroll
            for (int nt = 0; nt < 8; nt++)
                LDSM_X2_T(b[nt],
                          sv + ((s * 128 * VSH +
                                 (wnS + (j << 4) + bkrow) * VSH) + (nt << 3)) * 2);
#pragma unroll
            for (int mt = 0; mt < 2; mt++)
#pragma unroll
                for (int nt = 0; nt < 8; nt++)
                    mma_f16(oacc[mt][nt], pa[mt][j], b[nt]);
        }
        __syncthreads();   // k/v buffers free for next chunk
    }

    // ---- rowsum reduce + inv ----
#pragma unroll
    for (int mt = 0; mt < 2; mt++) {
        float r0 = rsum[mt][0], r1 = rsum[mt][1];
        r0 += __shfl_xor_sync(0xffffffffu, r0, 1);
        r0 += __shfl_xor_sync(0xffffffffu, r0, 2);
        r1 += __shfl_xor_sync(0xffffffffu, r1, 1);
        r1 += __shfl_xor_sync(0xffffffffu, r1, 2);
        if (t == 0) {
            atomicAdd(&rows_s[wm + (mt << 4) + g], r0);
            atomicAdd(&rows_s[wm + (mt << 4) + g + 8], r1);
        }
    }
    __syncthreads();
    if (tid < 64) {
        float sv_ = rows_s[tid];
        rowsum[(size_t)z * NPQ + m0 + tid] = sv_;
        rows_s[tid] = 1.0f / sv_;
    }
    __syncthreads();

    // ---- cross-ks O reduction via smem (reuse k buffer region) ----
    float* scratch = reinterpret_cast<float*>(sh + FK_OFF);  // 2*32*64 floats
    const int wpair = warp >> 1;
    if (warp & 1) {
#pragma unroll
        for (int mt = 0; mt < 2; mt++) {
            int rl = (mt << 4) + g;
#pragma unroll
            for (int nt = 0; nt < 8; nt++) {
                int n = (nt << 3) + 2 * t;
                *reinterpret_cast<float2*>(
                    &scratch[(wpair * 32 + rl) * 64 + n]) =
                    make_float2(oacc[mt][nt][0], oacc[mt][nt][1]);
                *reinterpret_cast<float2*>(
                    &scratch[(wpair * 32 + rl + 8) * 64 + n]) =
                    make_float2(oacc[mt][nt][2], oacc[mt][nt][3]);
            }
        }
    }
    __syncthreads();
    if (!(warp & 1)) {
#pragma unroll
        for (int mt = 0; mt < 2; mt++) {
            int rl = (mt << 4) + g;
            int mloc = wm + rl;
            float i0 = rows_s[mloc];
            float i1 = rows_s[mloc + 8];
#pragma unroll
            for (int nt = 0; nt < 8; nt++) {
                int n = (nt << 3) + 2 * t;
                float2 s0 = *reinterpret_cast<const float2*>(
                    &scratch[(wpair * 32 + rl) * 64 + n]);
                float2 s1 = *reinterpret_cast<const float2*>(
                    &scratch[(wpair * 32 + rl + 8) * 64 + n]);
                float2 o0, o1;
                o0.x = (oacc[mt][nt][0] + s0.x) * i0;
                o0.y = (oacc[mt][nt][1] + s0.y) * i0;
                o1.x = (oacc[mt][nt][2] + s1.x) * i1;
                o1.y = (oacc[mt][nt][3] + s1.y) * i1;
                *reinterpret_cast<float2*>(
                    Oz + (size_t)(m0 + mloc) * CDIM + n) = o0;
                *reinterpret_cast<float2*>(
                    Oz + (size_t)(m0 + mloc + 8) * CDIM + n) = o1;
            }
        }
    }
}

// ---------------------------------------------------------------------------
// A_avg  [R11 shape]
// ---------------------------------------------------------------------------
__global__ void __launch_bounds__(256) avg_kernel(
    const __half* __restrict__ P, const float* __restrict__ rowsum,
    float* __restrict__ Aavg)
{
    __shared__ float sinv[2][16];
    const int bp = 3 - (blockIdx.x >> 9);
    const int qp = blockIdx.x & 511;
    const int t = threadIdx.x;
    const int row = t >> 7;
    const int ch = t & 127;
    const int q = qp * 2 + row;

    if (t < 32) {
        int r2 = t >> 4, idx = t & 15;
        int b = idx >> 2, j = idx & 3;
        sinv[r2][idx] = 1.0f /
            rowsum[((size_t)(b * HH + bp * 4 + j)) * NPQ + qp * 2 + r2];
    }
    __syncthreads();

    float a0 = 0.f, a1 = 0.f, a2 = 0.f, a3 = 0.f;
    float a4 = 0.f, a5 = 0.f, a6 = 0.f, a7 = 0.f;
#pragma unroll
    for (int b = 0; b < 4; b++)
#pragma unroll
        for (int j = 0; j < 4; j++) {
            const __half* p = P +
                ((((size_t)(b * HH + bp * 4 + j)) << 10 | q) << 10) + ch * 8;
            uint4 u = *reinterpret_cast<const uint4*>(p);
            const __half2* h = reinterpret_cast<const __half2*>(&u);
            float f = sinv[row][b * 4 + j];
            float2 f0 = __half22float2(h[0]);
            float2 f1 = __half22float2(h[1]);
            float2 f2 = __half22float2(h[2]);
            float2 f3 = __half22float2(h[3]);
            a0 = fmaf(f0.x, f, a0); a1 = fmaf(f0.y, f, a1);
            a2 = fmaf(f1.x, f, a2); a3 = fmaf(f1.y, f, a3);
            a4 = fmaf(f2.x, f, a4); a5 = fmaf(f2.y, f, a5);
            a6 = fmaf(f3.x, f, a6); a7 = fmaf(f3.y, f, a7);
        }
    const float sc = 1.0f / 16.0f;
    float* dst = Aavg + (((size_t)(bp << 10 | q)) << 10) + ch * 8;
    *reinterpret_cast<float4*>(dst) =
        make_float4(a0 * sc, a1 * sc, a2 * sc, a3 * sc);
    *reinterpret_cast<float4*>(dst + 4) =
        make_float4(a4 * sc, a5 * sc, a6 * sc, a7 * sc);
}

// ---------------------------------------------------------------------------
#define PROJ_SMEM (2 * 128 * PH * 2)    // 20480 B

extern "C" void kernel_launch(void* const* d_in, const int* in_sizes, int n_in,
                              void* d_out, int out_size)
{
    const float* Q  = (const float*)d_in[0];
    const float* K  = (const float*)d_in[1];
    const float* Wq = (const float*)d_in[2];
    const float* bq = (const float*)d_in[3];
    const float* Wk = (const float*)d_in[4];
    const float* bk = (const float*)d_in[5];
    const float* Wv = (const float*)d_in[6];
    const float* bv = (const float*)d_in[7];

    float* O    = (float*)d_out;
    float* Aavg = O + (size_t)BB * NPQ * CDIM;

    static __half *pQh = nullptr, *pKh = nullptr, *pWh = nullptr;
    static __half *pq = nullptr, *pk = nullptr, *pv = nullptr, *pP = nullptr;
    static float* pR = nullptr;
    if (!pq) {
        cudaGetSymbolAddress((void**)&pQh, g_Qh);
        cudaGetSymbolAddress((void**)&pKh, g_Kh);
        cudaGetSymbolAddress((void**)&pWh, g_Wh);
        cudaGetSymbolAddress((void**)&pq, g_q);
        cudaGetSymbolAddress((void**)&pk, g_k);
        cudaGetSymbolAddress((void**)&pv, g_v);
        cudaGetSymbolAddress((void**)&pP, g_P);
        cudaGetSymbolAddress((void**)&pR, g_rowsum);
        cudaFuncSetAttribute(proj_gemm,
                             cudaFuncAttributeMaxDynamicSharedMemorySize, PROJ_SMEM);
        cudaFuncSetAttribute(fused_spv,
                             cudaFuncAttributeMaxDynamicSharedMemorySize, F_SMEM);
    }

    // 0) fp32 -> fp16 conversion
    const int NX4 = (BB * NPQ * CDIM) / 4;
    const int NW4 = (CDIM * CDIM) / 4;
    const int TOT4 = 2 * NX4 + 3 * NW4;
    f2h_all<<<(TOT4 + 255) / 256, 256>>>(Q, K, Wq, Wk, Wv, pQh, pKh, pWh);

    // 1) projections
    dim3 gp(CDIM / 128, (BB * NPQ) / 128, 3);
    proj_gemm<<<gp, 256, PROJ_SMEM>>>(pQh, pKh, pWh, bq, bk, bv, pq, pk, pv);

    // 2) fused: P, rowsum, O (FA2 fragments, 128 thr, 2 CTAs/SM)
    dim3 gf(NPQ / 64, BB * HH);
    fused_spv<<<gf, 128, F_SMEM>>>(pq, pk, pv, pP, pR, O);

    // 3) A_avg
    avg_kernel<<<BB * (NPQ / 2), 256>>>(pP, pR, Aavg);
}